// round 1
// baseline (speedup 1.0000x reference)
#include <cuda_runtime.h>

#define BD 2
#define DD 128
#define HH 128
#define WW 128
#define CIc 64
#define COc 64
#define NTAP 27
#define GRID_CELLS (BD*DD*HH*WW)

#define PTS 128
#define TPB 256

// Scratch (allocation-free rule: __device__ globals)
__device__ int   g_grid[GRID_CELLS];            // 16 MB voxel hash
__device__ float g_wt[NTAP*CIc*COc];            // weights transposed to [tap][ci][co]

// ---------------------------------------------------------------------------
__global__ void fill_grid_k() {
    int i = blockIdx.x * blockDim.x + threadIdx.x;
    if (i < GRID_CELLS/4) {
        ((int4*)g_grid)[i] = make_int4(-1,-1,-1,-1);
    }
}

__global__ void scatter_k(const int* __restrict__ coords, int n) {
    int i = blockIdx.x * blockDim.x + threadIdx.x;
    if (i < n) {
        int4 c = ((const int4*)coords)[i];  // b, z, y, x
        int lin = ((c.x*DD + c.y)*HH + c.z)*WW + c.w;
        g_grid[lin] = i;
    }
}

__global__ void transpose_w_k(const float* __restrict__ w) {
    // dst index i = (tap*64 + ci)*64 + co ; src = (co*27 + tap)*64 + ci
    int i = blockIdx.x * blockDim.x + threadIdx.x;
    if (i < NTAP*CIc*COc) {
        int co  = i & 63;
        int ci  = (i >> 6) & 63;
        int tap = i >> 12;
        g_wt[i] = w[(co*NTAP + tap)*CIc + ci];
    }
}

// ---------------------------------------------------------------------------
// Conv kernel: one CTA handles 128 points x 64 output channels.
// smem: feats_s [ci=64][pt=128] (32KB), w_s [ci=64][co=64] (16KB),
//       nidx_s [27][128] ints (13.5KB)  -> 62976 bytes dynamic smem.
__global__ void __launch_bounds__(TPB)
conv_k(const float* __restrict__ feats, const float* __restrict__ bias,
       const int* __restrict__ coords, float* __restrict__ out, int n)
{
    extern __shared__ float smem[];
    float* feats_s = smem;                         // 8192 floats
    float* w_s     = smem + 8192;                  // 4096 floats
    int*   nidx_s  = (int*)(smem + 8192 + 4096);   // 27*128 ints

    const int tid = threadIdx.x;
    const int p0  = blockIdx.x * PTS;

    // ---- prologue: neighbor indices for all 27 taps (one thread per point)
    if (tid < PTS) {
        int pt = p0 + tid;
        int4 c = make_int4(0,0,0,0);
        bool ok = (pt < n);
        if (ok) c = ((const int4*)coords)[pt];
        #pragma unroll
        for (int kd = 0; kd < 3; kd++)
        #pragma unroll
        for (int kh = 0; kh < 3; kh++)
        #pragma unroll
        for (int kw = 0; kw < 3; kw++) {
            int tap = (kd*3 + kh)*3 + kw;
            int idx = -1;
            if (ok) {
                int nz = c.y + kd - 1, ny = c.z + kh - 1, nx = c.w + kw - 1;
                if ((unsigned)nz < DD && (unsigned)ny < HH && (unsigned)nx < WW) {
                    int lin = ((c.x*DD + nz)*HH + ny)*WW + nx;
                    idx = g_grid[lin];
                }
            }
            nidx_s[tap*PTS + tid] = idx;
        }
    }

    // ---- accumulators: thread (tx,ty) owns pts [ty*8, ty*8+8) x co [tx*4, tx*4+4)
    const int tx = tid & 15;
    const int ty = tid >> 4;
    float acc[8][4];
    float4 bv = *(const float4*)(bias + tx*4);
    #pragma unroll
    for (int i = 0; i < 8; i++) {
        acc[i][0] = bv.x; acc[i][1] = bv.y; acc[i][2] = bv.z; acc[i][3] = bv.w;
    }

    for (int tap = 0; tap < NTAP; tap++) {
        __syncthreads();   // protects feats_s/w_s reuse; also orders prologue->gather

        // stage weights for this tap: linear 16KB copy (conflict-free)
        {
            const float4* wsrc = (const float4*)(g_wt + tap*(CIc*COc));
            float4* wdst = (float4*)w_s;
            #pragma unroll
            for (int j = 0; j < 4; j++)
                wdst[tid + j*TPB] = wsrc[tid + j*TPB];
        }

        // gather features transposed into [ci][pt]
        #pragma unroll
        for (int j = 0; j < 8; j++) {
            int c   = tid + j*TPB;      // 2048 float4 chunks
            int pt  = c & (PTS-1);      // consecutive lanes -> consecutive pt (no STS conflicts)
            int ci4 = c >> 7;
            int idx = nidx_s[tap*PTS + pt];
            float4 v = make_float4(0.f, 0.f, 0.f, 0.f);
            if (idx >= 0) v = *(const float4*)(feats + idx*CIc + ci4*4);
            feats_s[(ci4*4 + 0)*PTS + pt] = v.x;
            feats_s[(ci4*4 + 1)*PTS + pt] = v.y;
            feats_s[(ci4*4 + 2)*PTS + pt] = v.z;
            feats_s[(ci4*4 + 3)*PTS + pt] = v.w;
        }
        __syncthreads();

        // 128x64x64 fp32 tile-GEMM
        #pragma unroll 8
        for (int k = 0; k < CIc; k++) {
            float4 a0 = *(const float4*)(feats_s + k*PTS + ty*8);
            float4 a1 = *(const float4*)(feats_s + k*PTS + ty*8 + 4);
            float4 b  = *(const float4*)(w_s + k*COc + tx*4);
            float a[8] = {a0.x,a0.y,a0.z,a0.w,a1.x,a1.y,a1.z,a1.w};
            float bb[4] = {b.x,b.y,b.z,b.w};
            #pragma unroll
            for (int i = 0; i < 8; i++)
                #pragma unroll
                for (int j = 0; j < 4; j++)
                    acc[i][j] += a[i] * bb[j];
        }
    }

    // ---- epilogue
    #pragma unroll
    for (int i = 0; i < 8; i++) {
        int pt = p0 + ty*8 + i;
        if (pt < n) {
            float4 v = make_float4(acc[i][0], acc[i][1], acc[i][2], acc[i][3]);
            *(float4*)(out + pt*COc + tx*4) = v;
        }
    }
}

// ---------------------------------------------------------------------------
extern "C" void kernel_launch(void* const* d_in, const int* in_sizes, int n_in,
                              void* d_out, int out_size)
{
    const float* feats  = (const float*)d_in[0];
    const float* weight = (const float*)d_in[1];
    const float* bias   = (const float*)d_in[2];
    const int*   coords = (const int*)d_in[3];
    float* out = (float*)d_out;

    int n = in_sizes[0] / CIc;

    static bool attr_set = false;
    const int smem_bytes = (8192 + 4096) * 4 + NTAP*PTS*4;  // 62976
    if (!attr_set) {
        cudaFuncSetAttribute(conv_k, cudaFuncAttributeMaxDynamicSharedMemorySize, smem_bytes);
        attr_set = true;
    }

    fill_grid_k<<<GRID_CELLS/4/256, 256>>>();
    scatter_k<<<(n + 255)/256, 256>>>(coords, n);
    transpose_w_k<<<(NTAP*CIc*COc + 255)/256, 256>>>(weight);

    int nblocks = (n + PTS - 1) / PTS;
    conv_k<<<nblocks, TPB, smem_bytes>>>(feats, bias, coords, out, n);
}

// round 2
// speedup vs baseline: 4.8039x; 4.8039x over previous
#include <cuda_runtime.h>

#define DD 128
#define HH 128
#define WW 128
#define CIc 64
#define COc 64
#define NTAP 27
#define GRID_CELLS (2*DD*HH*WW)
#define NMAX 200000
#define PTS 128
#define TPB 256
#define GX 160

// Scratch (__device__ globals: allocation-free rule)
__device__ int   g_grid[GRID_CELLS];        // 16 MB voxel hash
__device__ float g_wt[NTAP*CIc*COc];        // weights transposed to [tap][ci][co]
__device__ int2  g_pairs[26*NMAX];          // per-tap (out_pt, in_idx) lists
__device__ int   g_cnt[26];                 // per-tap pair counts

// ---------------------------------------------------------------------------
__global__ void fill_grid_k() {
    int i = blockIdx.x * blockDim.x + threadIdx.x;
    if (i < GRID_CELLS/4)
        ((int4*)g_grid)[i] = make_int4(-1,-1,-1,-1);
    if (i < 26) g_cnt[i] = 0;
}

__global__ void scatter_k(const int* __restrict__ coords, int n) {
    int i = blockIdx.x * blockDim.x + threadIdx.x;
    if (i < n) {
        int4 c = ((const int4*)coords)[i];  // b, z, y, x
        int lin = ((c.x*DD + c.y)*HH + c.z)*WW + c.w;
        g_grid[lin] = i;
    }
}

__global__ void transpose_w_k(const float* __restrict__ w) {
    int i = blockIdx.x * blockDim.x + threadIdx.x;
    if (i < NTAP*CIc*COc) {
        int co  = i & 63;
        int ci  = (i >> 6) & 63;
        int tap = i >> 12;
        g_wt[i] = w[(co*NTAP + tap)*CIc + ci];
    }
}

// ---------------------------------------------------------------------------
// Build compacted per-tap pair lists for the 26 non-center taps.
__global__ void __launch_bounds__(TPB)
build_pairs_k(const int* __restrict__ coords, int n)
{
    __shared__ int nidx_s[26*TPB];
    __shared__ int cnt_s[26];
    __shared__ int base_s[26];

    const int tid = threadIdx.x;
    const int pt  = blockIdx.x * TPB + tid;

    if (tid < 26) cnt_s[tid] = 0;
    __syncthreads();

    int4 c = make_int4(0,0,0,0);
    bool ok = (pt < n);
    if (ok) c = ((const int4*)coords)[pt];

    #pragma unroll
    for (int t = 0; t < 26; t++) {
        int tap = (t < 13) ? t : t + 1;     // skip center tap 13
        int kd = tap / 9, kh = (tap / 3) % 3, kw = tap % 3;
        int idx = -1;
        if (ok) {
            int nz = c.y + kd - 1, ny = c.z + kh - 1, nx = c.w + kw - 1;
            if ((unsigned)nz < DD && (unsigned)ny < HH && (unsigned)nx < WW) {
                int lin = ((c.x*DD + nz)*HH + ny)*WW + nx;
                idx = g_grid[lin];
            }
        }
        nidx_s[t*TPB + tid] = idx;
        if (idx >= 0) atomicAdd(&cnt_s[t], 1);
    }
    __syncthreads();

    if (tid < 26) {
        base_s[tid] = atomicAdd(&g_cnt[tid], cnt_s[tid]);
        cnt_s[tid] = 0;
    }
    __syncthreads();

    #pragma unroll
    for (int t = 0; t < 26; t++) {
        int idx = nidx_s[t*TPB + tid];
        if (idx >= 0) {
            int pos = atomicAdd(&cnt_s[t], 1);
            g_pairs[t*NMAX + base_s[t] + pos] = make_int2(pt, idx);
        }
    }
}

// ---------------------------------------------------------------------------
// Center tap: dense out = bias + feats @ W[13]  (plain stores, no atomics)
__global__ void __launch_bounds__(TPB)
center_k(const float* __restrict__ feats, const float* __restrict__ bias,
         float* __restrict__ out, int n)
{
    extern __shared__ float smem[];
    float* feats_s = smem;          // [ci=64][pt=128]  32KB
    float* w_s     = smem + 8192;   // [ci=64][co=64]   16KB

    const int tid = threadIdx.x;
    const int p0  = blockIdx.x * PTS;
    const int tx = tid & 15;
    const int ty = tid >> 4;

    // stage center weights
    {
        const float4* wsrc = (const float4*)(g_wt + 13*(CIc*COc));
        float4* wdst = (float4*)w_s;
        #pragma unroll
        for (int j = 0; j < 4; j++)
            wdst[tid + j*TPB] = wsrc[tid + j*TPB];
    }

    // gather features transposed into [ci][pt]
    #pragma unroll
    for (int j = 0; j < 8; j++) {
        int c   = tid + j*TPB;
        int pt  = c & (PTS-1);
        int ci4 = c >> 7;
        int row = p0 + pt;
        float4 v = make_float4(0.f,0.f,0.f,0.f);
        if (row < n) v = *(const float4*)(feats + row*CIc + ci4*4);
        feats_s[(ci4*4 + 0)*PTS + pt] = v.x;
        feats_s[(ci4*4 + 1)*PTS + pt] = v.y;
        feats_s[(ci4*4 + 2)*PTS + pt] = v.z;
        feats_s[(ci4*4 + 3)*PTS + pt] = v.w;
    }
    __syncthreads();

    float acc[8][4];
    float4 bv = *(const float4*)(bias + tx*4);
    #pragma unroll
    for (int i = 0; i < 8; i++) {
        acc[i][0] = bv.x; acc[i][1] = bv.y; acc[i][2] = bv.z; acc[i][3] = bv.w;
    }

    #pragma unroll 8
    for (int k = 0; k < CIc; k++) {
        float4 a0 = *(const float4*)(feats_s + k*PTS + ty*8);
        float4 a1 = *(const float4*)(feats_s + k*PTS + ty*8 + 4);
        float4 b  = *(const float4*)(w_s + k*COc + tx*4);
        float a[8] = {a0.x,a0.y,a0.z,a0.w,a1.x,a1.y,a1.z,a1.w};
        float bb[4] = {b.x,b.y,b.z,b.w};
        #pragma unroll
        for (int i = 0; i < 8; i++)
            #pragma unroll
            for (int j = 0; j < 4; j++)
                acc[i][j] += a[i] * bb[j];
    }

    #pragma unroll
    for (int i = 0; i < 8; i++) {
        int pt = p0 + ty*8 + i;
        if (pt < n)
            *(float4*)(out + pt*COc + tx*4) =
                make_float4(acc[i][0], acc[i][1], acc[i][2], acc[i][3]);
    }
}

// ---------------------------------------------------------------------------
// Sparse taps: gathered GEMM over compacted pair lists, atomic accumulate.
// grid = (GX, 26); each block loops over 128-pair tiles of its tap.
__global__ void __launch_bounds__(TPB)
sparse_k(const float* __restrict__ feats, float* __restrict__ out)
{
    extern __shared__ float smem[];
    float* feats_s = smem;                        // 32KB
    float* w_s     = smem + 8192;                 // 16KB
    int2*  pair_s  = (int2*)(smem + 8192 + 4096); // 1KB

    const int tid = threadIdx.x;
    const int t   = blockIdx.y;                   // 0..25
    const int tap = (t < 13) ? t : t + 1;
    const int cnt = g_cnt[t];
    const int tx = tid & 15;
    const int ty = tid >> 4;

    // stage this tap's weights once
    {
        const float4* wsrc = (const float4*)(g_wt + tap*(CIc*COc));
        float4* wdst = (float4*)w_s;
        #pragma unroll
        for (int j = 0; j < 4; j++)
            wdst[tid + j*TPB] = wsrc[tid + j*TPB];
    }

    for (int tile = blockIdx.x; tile*PTS < cnt; tile += gridDim.x) {
        __syncthreads();   // protect pair_s/feats_s reuse (and first-iter w_s)

        if (tid < PTS) {
            int p = tile*PTS + tid;
            pair_s[tid] = (p < cnt) ? g_pairs[t*NMAX + p] : make_int2(-1,-1);
        }
        __syncthreads();

        // gather features transposed into [ci][pt]
        #pragma unroll
        for (int j = 0; j < 8; j++) {
            int c   = tid + j*TPB;
            int pt  = c & (PTS-1);
            int ci4 = c >> 7;
            int idx = pair_s[pt].y;
            float4 v = make_float4(0.f,0.f,0.f,0.f);
            if (idx >= 0) v = *(const float4*)(feats + idx*CIc + ci4*4);
            feats_s[(ci4*4 + 0)*PTS + pt] = v.x;
            feats_s[(ci4*4 + 1)*PTS + pt] = v.y;
            feats_s[(ci4*4 + 2)*PTS + pt] = v.z;
            feats_s[(ci4*4 + 3)*PTS + pt] = v.w;
        }
        __syncthreads();

        float acc[8][4];
        #pragma unroll
        for (int i = 0; i < 8; i++)
            #pragma unroll
            for (int j = 0; j < 4; j++)
                acc[i][j] = 0.f;

        #pragma unroll 8
        for (int k = 0; k < CIc; k++) {
            float4 a0 = *(const float4*)(feats_s + k*PTS + ty*8);
            float4 a1 = *(const float4*)(feats_s + k*PTS + ty*8 + 4);
            float4 b  = *(const float4*)(w_s + k*COc + tx*4);
            float a[8] = {a0.x,a0.y,a0.z,a0.w,a1.x,a1.y,a1.z,a1.w};
            float bb[4] = {b.x,b.y,b.z,b.w};
            #pragma unroll
            for (int i = 0; i < 8; i++)
                #pragma unroll
                for (int j = 0; j < 4; j++)
                    acc[i][j] += a[i] * bb[j];
        }

        #pragma unroll
        for (int i = 0; i < 8; i++) {
            int opt = pair_s[ty*8 + i].x;
            if (opt >= 0) {
                float* dst = out + opt*COc + tx*4;
                atomicAdd(dst + 0, acc[i][0]);
                atomicAdd(dst + 1, acc[i][1]);
                atomicAdd(dst + 2, acc[i][2]);
                atomicAdd(dst + 3, acc[i][3]);
            }
        }
    }
}

// ---------------------------------------------------------------------------
extern "C" void kernel_launch(void* const* d_in, const int* in_sizes, int n_in,
                              void* d_out, int out_size)
{
    const float* feats  = (const float*)d_in[0];
    const float* weight = (const float*)d_in[1];
    const float* bias   = (const float*)d_in[2];
    const int*   coords = (const int*)d_in[3];
    float* out = (float*)d_out;

    int n = in_sizes[0] / CIc;

    static bool attr_set = false;
    const int smem_center = (8192 + 4096) * 4;           // 49152
    const int smem_sparse = (8192 + 4096) * 4 + PTS*8;   // 50176
    if (!attr_set) {
        cudaFuncSetAttribute(center_k, cudaFuncAttributeMaxDynamicSharedMemorySize, smem_center);
        cudaFuncSetAttribute(sparse_k, cudaFuncAttributeMaxDynamicSharedMemorySize, smem_sparse);
        attr_set = true;
    }

    fill_grid_k<<<GRID_CELLS/4/256, 256>>>();
    scatter_k<<<(n + 255)/256, 256>>>(coords, n);
    transpose_w_k<<<(NTAP*CIc*COc + 255)/256, 256>>>(weight);
    build_pairs_k<<<(n + TPB - 1)/TPB, TPB>>>(coords, n);

    int nblocks = (n + PTS - 1) / PTS;
    center_k<<<nblocks, TPB, smem_center>>>(feats, bias, out, n);

    dim3 sgrid(GX, 26);
    sparse_k<<<sgrid, TPB, smem_sparse>>>(feats, out);
}

// round 3
// speedup vs baseline: 6.1485x; 1.2799x over previous
#include <cuda_runtime.h>

#define DD 128
#define HH 128
#define WW 128
#define CIc 64
#define COc 64
#define NTAP 27
#define GRID_CELLS (2*DD*HH*WW)
#define NMAX 200000
#define PTS 128
#define TPB 256
#define GX 160

// Scratch (__device__ globals: allocation-free rule)
__device__ int   g_grid[GRID_CELLS];        // 16 MB voxel hash
__device__ float g_wt[NTAP*CIc*COc];        // weights transposed to [tap][ci][co]
__device__ int2  g_pairs[NTAP*NMAX];        // per-tap (out_pt, in_idx) lists (tap 13 unused)
__device__ int   g_cnt[13*32];              // per-tap-pair counts, 128B padded

// ---------------------------------------------------------------------------
__global__ void fill_grid_k() {
    int i = blockIdx.x * blockDim.x + threadIdx.x;
    if (i < GRID_CELLS/4)
        ((int4*)g_grid)[i] = make_int4(-1,-1,-1,-1);
    if (i < 13*32) g_cnt[i] = 0;
}

__global__ void scatter_k(const int* __restrict__ coords, int n) {
    int i = blockIdx.x * blockDim.x + threadIdx.x;
    if (i < n) {
        int4 c = ((const int4*)coords)[i];  // b, z, y, x
        int lin = ((c.x*DD + c.y)*HH + c.z)*WW + c.w;
        g_grid[lin] = i;
    }
}

__global__ void transpose_w_k(const float* __restrict__ w) {
    int i = blockIdx.x * blockDim.x + threadIdx.x;
    if (i < NTAP*CIc*COc) {
        int co  = i & 63;
        int ci  = (i >> 6) & 63;
        int tap = i >> 12;
        g_wt[i] = w[(co*NTAP + tap)*CIc + ci];
    }
}

// ---------------------------------------------------------------------------
// Build compacted per-tap pair lists. Mirror trick: one lookup at offset delta
// yields pair (p,q) for tap t AND pair (q,p) for tap 26-t, sharing one counter.
__global__ void __launch_bounds__(TPB)
build_pairs_k(const int* __restrict__ coords, int n)
{
    const int tid  = threadIdx.x;
    const int lane = tid & 31;
    const int pt   = blockIdx.x * TPB + tid;

    int4 c = make_int4(0,0,0,0);
    bool ok = (pt < n);
    if (ok) c = ((const int4*)coords)[pt];
    int lin0 = ((c.x*DD + c.y)*HH + c.z)*WW + c.w;

    #pragma unroll
    for (int t = 0; t < 13; t++) {      // taps 0..12; mirror gives 14..26
        int kd = t/9 - 1, kh = (t/3)%3 - 1, kw = t%3 - 1;
        int idx = -1;
        if (ok) {
            int nz = c.y + kd, ny = c.z + kh, nx = c.w + kw;
            if ((unsigned)nz < DD && (unsigned)ny < HH && (unsigned)nx < WW)
                idx = __ldg(&g_grid[lin0 + (kd*HH + kh)*WW + kw]);
        }
        unsigned m = __ballot_sync(0xffffffffu, idx >= 0);
        if (m) {
            int leader = __ffs(m) - 1;
            int base = 0;
            if (lane == leader) base = atomicAdd(&g_cnt[t*32], __popc(m));
            base = __shfl_sync(0xffffffffu, base, leader);
            if (idx >= 0) {
                int pos = base + __popc(m & ((1u << lane) - 1));
                g_pairs[t*NMAX + pos]      = make_int2(pt, idx);
                g_pairs[(26-t)*NMAX + pos] = make_int2(idx, pt);
            }
        }
    }
}

// ---------------------------------------------------------------------------
// Center tap: dense out = bias + feats @ W[13]  (plain stores, no atomics)
__global__ void __launch_bounds__(TPB)
center_k(const float* __restrict__ feats, const float* __restrict__ bias,
         float* __restrict__ out, int n)
{
    extern __shared__ float smem[];
    float* feats_s = smem;          // [ci=64][pt=128]  32KB
    float* w_s     = smem + 8192;   // [ci=64][co=64]   16KB

    const int tid = threadIdx.x;
    const int p0  = blockIdx.x * PTS;
    const int tx = tid & 15;
    const int ty = tid >> 4;

    {
        const float4* wsrc = (const float4*)(g_wt + 13*(CIc*COc));
        float4* wdst = (float4*)w_s;
        #pragma unroll
        for (int j = 0; j < 4; j++)
            wdst[tid + j*TPB] = wsrc[tid + j*TPB];
    }

    #pragma unroll
    for (int j = 0; j < 8; j++) {
        int c   = tid + j*TPB;
        int pt  = c & (PTS-1);
        int ci4 = c >> 7;
        int row = p0 + pt;
        float4 v = make_float4(0.f,0.f,0.f,0.f);
        if (row < n) v = *(const float4*)(feats + row*CIc + ci4*4);
        feats_s[(ci4*4 + 0)*PTS + pt] = v.x;
        feats_s[(ci4*4 + 1)*PTS + pt] = v.y;
        feats_s[(ci4*4 + 2)*PTS + pt] = v.z;
        feats_s[(ci4*4 + 3)*PTS + pt] = v.w;
    }
    __syncthreads();

    float acc[8][4];
    float4 bv = *(const float4*)(bias + tx*4);
    #pragma unroll
    for (int i = 0; i < 8; i++) {
        acc[i][0] = bv.x; acc[i][1] = bv.y; acc[i][2] = bv.z; acc[i][3] = bv.w;
    }

    #pragma unroll 8
    for (int k = 0; k < CIc; k++) {
        float4 a0 = *(const float4*)(feats_s + k*PTS + ty*8);
        float4 a1 = *(const float4*)(feats_s + k*PTS + ty*8 + 4);
        float4 b  = *(const float4*)(w_s + k*COc + tx*4);
        float a[8] = {a0.x,a0.y,a0.z,a0.w,a1.x,a1.y,a1.z,a1.w};
        float bb[4] = {b.x,b.y,b.z,b.w};
        #pragma unroll
        for (int i = 0; i < 8; i++)
            #pragma unroll
            for (int j = 0; j < 4; j++)
                acc[i][j] += a[i] * bb[j];
    }

    #pragma unroll
    for (int i = 0; i < 8; i++) {
        int pt = p0 + ty*8 + i;
        if (pt < n)
            *(float4*)(out + pt*COc + tx*4) =
                make_float4(acc[i][0], acc[i][1], acc[i][2], acc[i][3]);
    }
}

// ---------------------------------------------------------------------------
// Sparse taps: gathered GEMM over compacted pair lists, vector RED accumulate.
__global__ void __launch_bounds__(TPB)
sparse_k(const float* __restrict__ feats, float* __restrict__ out)
{
    extern __shared__ float smem[];
    float* feats_s = smem;                        // 32KB
    float* w_s     = smem + 8192;                 // 16KB
    int2*  pair_s  = (int2*)(smem + 8192 + 4096); // 1KB

    const int tid = threadIdx.x;
    const int t   = blockIdx.y;                   // 0..25
    const int tap = (t < 13) ? t : t + 1;
    const int cnt = g_cnt[((tap < 13) ? tap : 26 - tap) * 32];
    const int tx = tid & 15;
    const int ty = tid >> 4;

    {
        const float4* wsrc = (const float4*)(g_wt + tap*(CIc*COc));
        float4* wdst = (float4*)w_s;
        #pragma unroll
        for (int j = 0; j < 4; j++)
            wdst[tid + j*TPB] = wsrc[tid + j*TPB];
    }

    for (int tile = blockIdx.x; tile*PTS < cnt; tile += gridDim.x) {
        __syncthreads();

        if (tid < PTS) {
            int p = tile*PTS + tid;
            pair_s[tid] = (p < cnt) ? g_pairs[tap*NMAX + p] : make_int2(-1,-1);
        }
        __syncthreads();

        #pragma unroll
        for (int j = 0; j < 8; j++) {
            int c   = tid + j*TPB;
            int pt  = c & (PTS-1);
            int ci4 = c >> 7;
            int idx = pair_s[pt].y;
            float4 v = make_float4(0.f,0.f,0.f,0.f);
            if (idx >= 0) v = *(const float4*)(feats + idx*CIc + ci4*4);
            feats_s[(ci4*4 + 0)*PTS + pt] = v.x;
            feats_s[(ci4*4 + 1)*PTS + pt] = v.y;
            feats_s[(ci4*4 + 2)*PTS + pt] = v.z;
            feats_s[(ci4*4 + 3)*PTS + pt] = v.w;
        }
        __syncthreads();

        float acc[8][4];
        #pragma unroll
        for (int i = 0; i < 8; i++)
            #pragma unroll
            for (int j = 0; j < 4; j++)
                acc[i][j] = 0.f;

        #pragma unroll 8
        for (int k = 0; k < CIc; k++) {
            float4 a0 = *(const float4*)(feats_s + k*PTS + ty*8);
            float4 a1 = *(const float4*)(feats_s + k*PTS + ty*8 + 4);
            float4 b  = *(const float4*)(w_s + k*COc + tx*4);
            float a[8] = {a0.x,a0.y,a0.z,a0.w,a1.x,a1.y,a1.z,a1.w};
            float bb[4] = {b.x,b.y,b.z,b.w};
            #pragma unroll
            for (int i = 0; i < 8; i++)
                #pragma unroll
                for (int j = 0; j < 4; j++)
                    acc[i][j] += a[i] * bb[j];
        }

        #pragma unroll
        for (int i = 0; i < 8; i++) {
            int opt = pair_s[ty*8 + i].x;
            if (opt >= 0) {
                float* dst = out + opt*COc + tx*4;
                asm volatile("red.global.add.v4.f32 [%0], {%1, %2, %3, %4};"
                             :: "l"(dst),
                                "f"(acc[i][0]), "f"(acc[i][1]),
                                "f"(acc[i][2]), "f"(acc[i][3])
                             : "memory");
            }
        }
    }
}

// ---------------------------------------------------------------------------
extern "C" void kernel_launch(void* const* d_in, const int* in_sizes, int n_in,
                              void* d_out, int out_size)
{
    const float* feats  = (const float*)d_in[0];
    const float* weight = (const float*)d_in[1];
    const float* bias   = (const float*)d_in[2];
    const int*   coords = (const int*)d_in[3];
    float* out = (float*)d_out;

    int n = in_sizes[0] / CIc;

    static bool attr_set = false;
    const int smem_center = (8192 + 4096) * 4;           // 49152
    const int smem_sparse = (8192 + 4096) * 4 + PTS*8;   // 50176
    if (!attr_set) {
        cudaFuncSetAttribute(center_k, cudaFuncAttributeMaxDynamicSharedMemorySize, smem_center);
        cudaFuncSetAttribute(sparse_k, cudaFuncAttributeMaxDynamicSharedMemorySize, smem_sparse);
        attr_set = true;
    }

    fill_grid_k<<<GRID_CELLS/4/256, 256>>>();
    scatter_k<<<(n + 255)/256, 256>>>(coords, n);
    transpose_w_k<<<(NTAP*CIc*COc + 255)/256, 256>>>(weight);
    build_pairs_k<<<(n + TPB - 1)/TPB, TPB>>>(coords, n);

    int nblocks = (n + PTS - 1) / PTS;
    center_k<<<nblocks, TPB, smem_center>>>(feats, bias, out, n);

    dim3 sgrid(GX, 26);
    sparse_k<<<sgrid, TPB, smem_sparse>>>(feats, out);
}

// round 5
// speedup vs baseline: 6.5133x; 1.0593x over previous
#include <cuda_runtime.h>

#define DD 128
#define HH 128
#define WW 128
#define CIc 64
#define COc 64
#define NTAP 27
#define GRID_CELLS (2*DD*HH*WW)
#define NMAX 200000
#define PTS 128
#define TPB 256
#define GX 128

// Scratch (__device__ globals: allocation-free rule).
// g_grid stores idx+1; 0 = empty. Zero at module load; center_k re-zeros the
// touched cells every call, so the invariant "g_grid all zero on entry" holds.
__device__ int   g_grid[GRID_CELLS];        // voxel hash (idx+1, 0=empty)
__device__ float g_wt[NTAP*CIc*COc];        // weights transposed to [tap][ci][co]
__device__ int2  g_pairs[NTAP*NMAX];        // per-tap (out_pt, in_idx) lists (tap 13 unused)
__device__ int   g_cnt[13*32];              // per-tap-pair counts, 128B padded

// ---------------------------------------------------------------------------
// Fused prep: scatter coords into hash, transpose weights, reset counters.
__global__ void __launch_bounds__(256)
prep_k(const int* __restrict__ coords, const float* __restrict__ w, int n)
{
    int i = blockIdx.x * blockDim.x + threadIdx.x;

    if (i < n) {
        int4 c = ((const int4*)coords)[i];  // b, z, y, x
        int lin = ((c.x*DD + c.y)*HH + c.z)*WW + c.w;
        g_grid[lin] = i + 1;
    }

    if (i < NTAP*CIc*COc) {
        int co  = i & 63;
        int ci  = (i >> 6) & 63;
        int tap = i >> 12;
        g_wt[i] = w[(co*NTAP + tap)*CIc + ci];
    }

    if (i < 13*32) g_cnt[i] = 0;
}

// ---------------------------------------------------------------------------
// Build compacted per-tap pair lists. Mirror trick: one lookup at offset delta
// yields pair (p,q) for tap t AND pair (q,p) for tap 26-t, sharing one counter.
// All 13 loads issued up front (MLP=13) before the ballot/compaction chain.
__global__ void __launch_bounds__(TPB)
build_pairs_k(const int* __restrict__ coords, int n)
{
    const int tid  = threadIdx.x;
    const int lane = tid & 31;
    const int pt   = blockIdx.x * TPB + tid;

    int4 c = make_int4(0,0,0,0);
    bool ok = (pt < n);
    if (ok) c = ((const int4*)coords)[pt];
    int lin0 = ((c.x*DD + c.y)*HH + c.z)*WW + c.w;

    // Phase 1: issue all 13 independent grid lookups (MLP=13)
    int idxs[13];
    #pragma unroll
    for (int t = 0; t < 13; t++) {
        int kd = t/9 - 1, kh = (t/3)%3 - 1, kw = t%3 - 1;
        int v = 0;
        if (ok) {
            int nz = c.y + kd, ny = c.z + kh, nx = c.w + kw;
            if ((unsigned)nz < DD && (unsigned)ny < HH && (unsigned)nx < WW)
                v = __ldg(&g_grid[lin0 + (kd*HH + kh)*WW + kw]);
        }
        idxs[t] = v - 1;   // -1 if empty/OOB
    }

    // Phase 2: per-tap warp-aggregated compaction
    #pragma unroll
    for (int t = 0; t < 13; t++) {
        int idx = idxs[t];
        unsigned m = __ballot_sync(0xffffffffu, idx >= 0);
        if (m) {
            int leader = __ffs(m) - 1;
            int base = 0;
            if (lane == leader) base = atomicAdd(&g_cnt[t*32], __popc(m));
            base = __shfl_sync(0xffffffffu, base, leader);
            if (idx >= 0) {
                int pos = base + __popc(m & ((1u << lane) - 1));
                g_pairs[t*NMAX + pos]      = make_int2(pt, idx);
                g_pairs[(26-t)*NMAX + pos] = make_int2(idx, pt);
            }
        }
    }
}

// ---------------------------------------------------------------------------
// Center tap: dense out = bias + feats @ W[13] (plain stores, no atomics).
// Prologue also zeros this tile's g_grid cells (cleanup fused; runs after
// build_pairs on the stream, so no one reads the grid anymore this call).
__global__ void __launch_bounds__(TPB)
center_k(const float* __restrict__ feats, const float* __restrict__ bias,
         const int* __restrict__ coords, float* __restrict__ out, int n)
{
    extern __shared__ float smem[];
    float* feats_s = smem;          // [ci=64][pt=128]  32KB
    float* w_s     = smem + 8192;   // [ci=64][co=64]   16KB

    const int tid = threadIdx.x;
    const int p0  = blockIdx.x * PTS;
    const int tx = tid & 15;
    const int ty = tid >> 4;

    // fused grid cleanup for this tile's points
    if (tid < PTS) {
        int pt = p0 + tid;
        if (pt < n) {
            int4 c = ((const int4*)coords)[pt];
            int lin = ((c.x*DD + c.y)*HH + c.z)*WW + c.w;
            g_grid[lin] = 0;
        }
    }

    {
        const float4* wsrc = (const float4*)(g_wt + 13*(CIc*COc));
        float4* wdst = (float4*)w_s;
        #pragma unroll
        for (int j = 0; j < 4; j++)
            wdst[tid + j*TPB] = wsrc[tid + j*TPB];
    }

    #pragma unroll
    for (int j = 0; j < 8; j++) {
        int c   = tid + j*TPB;
        int pt  = c & (PTS-1);
        int ci4 = c >> 7;
        int row = p0 + pt;
        float4 v = make_float4(0.f,0.f,0.f,0.f);
        if (row < n) v = *(const float4*)(feats + row*CIc + ci4*4);
        feats_s[(ci4*4 + 0)*PTS + pt] = v.x;
        feats_s[(ci4*4 + 1)*PTS + pt] = v.y;
        feats_s[(ci4*4 + 2)*PTS + pt] = v.z;
        feats_s[(ci4*4 + 3)*PTS + pt] = v.w;
    }
    __syncthreads();

    float acc[8][4];
    float4 bv = *(const float4*)(bias + tx*4);
    #pragma unroll
    for (int i = 0; i < 8; i++) {
        acc[i][0] = bv.x; acc[i][1] = bv.y; acc[i][2] = bv.z; acc[i][3] = bv.w;
    }

    #pragma unroll 8
    for (int k = 0; k < CIc; k++) {
        float4 a0 = *(const float4*)(feats_s + k*PTS + ty*8);
        float4 a1 = *(const float4*)(feats_s + k*PTS + ty*8 + 4);
        float4 b  = *(const float4*)(w_s + k*COc + tx*4);
        float a[8] = {a0.x,a0.y,a0.z,a0.w,a1.x,a1.y,a1.z,a1.w};
        float bb[4] = {b.x,b.y,b.z,b.w};
        #pragma unroll
        for (int i = 0; i < 8; i++)
            #pragma unroll
            for (int j = 0; j < 4; j++)
                acc[i][j] += a[i] * bb[j];
    }

    #pragma unroll
    for (int i = 0; i < 8; i++) {
        int pt = p0 + ty*8 + i;
        if (pt < n)
            *(float4*)(out + pt*COc + tx*4) =
                make_float4(acc[i][0], acc[i][1], acc[i][2], acc[i][3]);
    }
}

// ---------------------------------------------------------------------------
// Sparse taps: gathered GEMM over compacted pair lists, vector RED accumulate.
__global__ void __launch_bounds__(TPB)
sparse_k(const float* __restrict__ feats, float* __restrict__ out)
{
    extern __shared__ float smem[];
    float* feats_s = smem;                        // 32KB
    float* w_s     = smem + 8192;                 // 16KB
    int2*  pair_s  = (int2*)(smem + 8192 + 4096); // 1KB

    const int tid = threadIdx.x;
    const int t   = blockIdx.y;                   // 0..25
    const int tap = (t < 13) ? t : t + 1;
    const int cnt = g_cnt[((tap < 13) ? tap : 26 - tap) * 32];
    const int tx = tid & 15;
    const int ty = tid >> 4;

    {
        const float4* wsrc = (const float4*)(g_wt + tap*(CIc*COc));
        float4* wdst = (float4*)w_s;
        #pragma unroll
        for (int j = 0; j < 4; j++)
            wdst[tid + j*TPB] = wsrc[tid + j*TPB];
    }

    for (int tile = blockIdx.x; tile*PTS < cnt; tile += gridDim.x) {
        __syncthreads();

        if (tid < PTS) {
            int p = tile*PTS + tid;
            pair_s[tid] = (p < cnt) ? g_pairs[tap*NMAX + p] : make_int2(-1,-1);
        }
        __syncthreads();

        #pragma unroll
        for (int j = 0; j < 8; j++) {
            int c   = tid + j*TPB;
            int pt  = c & (PTS-1);
            int ci4 = c >> 7;
            int idx = pair_s[pt].y;
            float4 v = make_float4(0.f,0.f,0.f,0.f);
            if (idx >= 0) v = *(const float4*)(feats + idx*CIc + ci4*4);
            feats_s[(ci4*4 + 0)*PTS + pt] = v.x;
            feats_s[(ci4*4 + 1)*PTS + pt] = v.y;
            feats_s[(ci4*4 + 2)*PTS + pt] = v.z;
            feats_s[(ci4*4 + 3)*PTS + pt] = v.w;
        }
        __syncthreads();

        float acc[8][4];
        #pragma unroll
        for (int i = 0; i < 8; i++)
            #pragma unroll
            for (int j = 0; j < 4; j++)
                acc[i][j] = 0.f;

        #pragma unroll 8
        for (int k = 0; k < CIc; k++) {
            float4 a0 = *(const float4*)(feats_s + k*PTS + ty*8);
            float4 a1 = *(const float4*)(feats_s + k*PTS + ty*8 + 4);
            float4 b  = *(const float4*)(w_s + k*COc + tx*4);
            float a[8] = {a0.x,a0.y,a0.z,a0.w,a1.x,a1.y,a1.z,a1.w};
            float bb[4] = {b.x,b.y,b.z,b.w};
            #pragma unroll
            for (int i = 0; i < 8; i++)
                #pragma unroll
                for (int j = 0; j < 4; j++)
                    acc[i][j] += a[i] * bb[j];
        }

        #pragma unroll
        for (int i = 0; i < 8; i++) {
            int opt = pair_s[ty*8 + i].x;
            if (opt >= 0) {
                float* dst = out + opt*COc + tx*4;
                asm volatile("red.global.add.v4.f32 [%0], {%1, %2, %3, %4};"
                             :: "l"(dst),
                                "f"(acc[i][0]), "f"(acc[i][1]),
                                "f"(acc[i][2]), "f"(acc[i][3])
                             : "memory");
            }
        }
    }
}

// ---------------------------------------------------------------------------
extern "C" void kernel_launch(void* const* d_in, const int* in_sizes, int n_in,
                              void* d_out, int out_size)
{
    const float* feats  = (const float*)d_in[0];
    const float* weight = (const float*)d_in[1];
    const float* bias   = (const float*)d_in[2];
    const int*   coords = (const int*)d_in[3];
    float* out = (float*)d_out;

    int n = in_sizes[0] / CIc;

    static bool attr_set = false;
    const int smem_center = (8192 + 4096) * 4;           // 49152
    const int smem_sparse = (8192 + 4096) * 4 + PTS*8;   // 50176
    if (!attr_set) {
        cudaFuncSetAttribute(center_k, cudaFuncAttributeMaxDynamicSharedMemorySize, smem_center);
        cudaFuncSetAttribute(sparse_k, cudaFuncAttributeMaxDynamicSharedMemorySize, smem_sparse);
        attr_set = true;
    }

    int prep_items = (NTAP*CIc*COc > n) ? NTAP*CIc*COc : n;
    prep_k<<<(prep_items + 255)/256, 256>>>(coords, weight, n);
    build_pairs_k<<<(n + TPB - 1)/TPB, TPB>>>(coords, n);

    int nblocks = (n + PTS - 1) / PTS;
    center_k<<<nblocks, TPB, smem_center>>>(feats, bias, coords, out, n);

    dim3 sgrid(GX, 26);
    sparse_k<<<sgrid, TPB, smem_sparse>>>(feats, out);
}

// round 7
// speedup vs baseline: 7.7841x; 1.1951x over previous
#include <cuda_runtime.h>
#include <cuda_bf16.h>
#include <cstdint>

#define DD 128
#define HH 128
#define WW 128
#define CIc 64
#define COc 64
#define NTAP 27
#define GRID_CELLS (2*DD*HH*WW)
#define NMAX 200000
#define TPB 256
#define GXS 80

// smem layout (bytes). A/B tiles use 144B row stride (72 bf16) so ldmatrix
// 16B row-chunks land on distinct granules (stride = 9 granules, odd -> all 8).
#define SM_PAIRS 0
#define SM_AB 1024
#define SM_AS (1024 + 18432)
#define SM_BB (1024 + 2*18432)
#define SM_BS (1024 + 2*18432 + 9216)
#define SM_TOTAL (1024 + 2*18432 + 2*9216)   // 56320

// Scratch (__device__ globals: allocation-free rule).
__device__ int   g_grid[GRID_CELLS];             // voxel hash (idx+1, 0=empty)
__device__ __nv_bfloat16 g_wtb[NTAP*CIc*COc];    // [tap][co][ci] bf16 hi
__device__ __nv_bfloat16 g_wts[NTAP*CIc*COc];    // [tap][co][ci] bf16 lo (residual)
__device__ int2  g_pairs[NTAP*NMAX];             // per-tap (out_pt, in_idx)
__device__ int   g_cnt[13*32];                   // mirror-shared counts, padded

// ---------------------------------------------------------------------------
__device__ __forceinline__ uint32_t smem_u32(const void* p) {
    uint32_t a;
    asm("{ .reg .u64 t; cvta.to.shared.u64 t, %1; cvt.u32.u64 %0, t; }" : "=r"(a) : "l"(p));
    return a;
}
// pack {hi16=cvt(a), lo16=cvt(b)}
__device__ __forceinline__ uint32_t bf2(float a, float b) {
    uint32_t r; asm("cvt.rn.bf16x2.f32 %0, %1, %2;" : "=r"(r) : "f"(a), "f"(b));
    return r;
}
__device__ __forceinline__ void ldsm4(uint32_t a, uint32_t r[4]) {
    asm volatile("ldmatrix.sync.aligned.m8n8.x4.shared.b16 {%0,%1,%2,%3}, [%4];"
        : "=r"(r[0]), "=r"(r[1]), "=r"(r[2]), "=r"(r[3]) : "r"(a));
}
__device__ __forceinline__ void ldsm2(uint32_t a, uint32_t r[2]) {
    asm volatile("ldmatrix.sync.aligned.m8n8.x2.shared.b16 {%0,%1}, [%2];"
        : "=r"(r[0]), "=r"(r[1]) : "r"(a));
}
__device__ __forceinline__ void mma_bf16(float c[4], const uint32_t a[4], const uint32_t b[2]) {
    asm volatile("mma.sync.aligned.m16n8k16.row.col.f32.bf16.bf16.f32 "
        "{%0,%1,%2,%3}, {%4,%5,%6,%7}, {%8,%9}, {%0,%1,%2,%3};"
        : "+f"(c[0]), "+f"(c[1]), "+f"(c[2]), "+f"(c[3])
        : "r"(a[0]), "r"(a[1]), "r"(a[2]), "r"(a[3]), "r"(b[0]), "r"(b[1]));
}
__device__ __forceinline__ void sts64(uint32_t a, uint32_t x, uint32_t y) {
    asm volatile("st.shared.v2.b32 [%0], {%1,%2};" :: "r"(a), "r"(x), "r"(y) : "memory");
}
__device__ __forceinline__ void sts128(uint32_t a, uint4 v) {
    asm volatile("st.shared.v4.b32 [%0], {%1,%2,%3,%4};"
        :: "r"(a), "r"(v.x), "r"(v.y), "r"(v.z), "r"(v.w) : "memory");
}

// ---------------------------------------------------------------------------
// Fused prep: scatter hash, bf16-split weight transpose, reset counters.
__global__ void __launch_bounds__(256)
prep_k(const int* __restrict__ coords, const float* __restrict__ w, int n)
{
    int i = blockIdx.x * blockDim.x + threadIdx.x;
    if (i < n) {
        int4 c = ((const int4*)coords)[i];  // b, z, y, x
        g_grid[((c.x*DD + c.y)*HH + c.z)*WW + c.w] = i + 1;
    }
    if (i < NTAP*CIc*COc) {
        int ci  = i & 63;
        int co  = (i >> 6) & 63;
        int tap = i >> 12;
        float v = w[(co*NTAP + tap)*CIc + ci];
        __nv_bfloat16 h = __float2bfloat16(v);
        int dst = (tap*COc + co)*CIc + ci;
        g_wtb[dst] = h;
        g_wts[dst] = __float2bfloat16(v - __bfloat162float(h));
    }
    if (i < 13*32) g_cnt[i] = 0;
}

// ---------------------------------------------------------------------------
// Build compacted per-tap pair lists (mirror trick + batched MLP=13 loads).
__global__ void __launch_bounds__(TPB)
build_pairs_k(const int* __restrict__ coords, int n)
{
    const int tid  = threadIdx.x;
    const int lane = tid & 31;
    const int pt   = blockIdx.x * TPB + tid;

    int4 c = make_int4(0,0,0,0);
    bool ok = (pt < n);
    if (ok) c = ((const int4*)coords)[pt];
    int lin0 = ((c.x*DD + c.y)*HH + c.z)*WW + c.w;

    int idxs[13];
    #pragma unroll
    for (int t = 0; t < 13; t++) {
        int kd = t/9 - 1, kh = (t/3)%3 - 1, kw = t%3 - 1;
        int v = 0;
        if (ok) {
            int nz = c.y + kd, ny = c.z + kh, nx = c.w + kw;
            if ((unsigned)nz < DD && (unsigned)ny < HH && (unsigned)nx < WW)
                v = __ldg(&g_grid[lin0 + (kd*HH + kh)*WW + kw]);
        }
        idxs[t] = v - 1;
    }

    #pragma unroll
    for (int t = 0; t < 13; t++) {
        int idx = idxs[t];
        unsigned m = __ballot_sync(0xffffffffu, idx >= 0);
        if (m) {
            int leader = __ffs(m) - 1;
            int base = 0;
            if (lane == leader) base = atomicAdd(&g_cnt[t*32], __popc(m));
            base = __shfl_sync(0xffffffffu, base, leader);
            if (idx >= 0) {
                int pos = base + __popc(m & ((1u << lane) - 1));
                g_pairs[t*NMAX + pos]      = make_int2(pt, idx);
                g_pairs[(26-t)*NMAX + pos] = make_int2(idx, pt);
            }
        }
    }
}

// ---------------------------------------------------------------------------
// Shared staging / compute helpers for the mma kernels.

// stage this tap's weights into smem as bf16 hi/lo, [co][72] layout
__device__ __forceinline__ void stage_B(uint32_t sb, int tap) {
    const uint4* wb = (const uint4*)(g_wtb + tap*(CIc*COc));
    const uint4* ws = (const uint4*)(g_wts + tap*(CIc*COc));
    #pragma unroll
    for (int j = 0; j < 2; j++) {
        int ch  = threadIdx.x + j*TPB;      // 512 chunks of 8 bf16
        int co  = ch >> 3, ci8 = ch & 7;
        uint32_t off = co*144 + ci8*16;
        sts128(sb + SM_BB + off, wb[ch]);
        sts128(sb + SM_BS + off, ws[ch]);
    }
}

// gather 128 feature rows (via pair_s[].y), bf16-split, store [pt][72] hi/lo
__device__ __forceinline__ void stage_A(uint32_t sb, const float* __restrict__ feats,
                                        const int2* pair_s) {
    #pragma unroll
    for (int j = 0; j < 8; j++) {
        int id  = threadIdx.x + j*TPB;      // 2048 float4 chunks
        int ci4 = id & 15;
        int pt  = id >> 4;
        int idx = pair_s[pt].y;
        float4 v = make_float4(0.f,0.f,0.f,0.f);
        if (idx >= 0) v = ((const float4*)feats)[idx*16 + ci4];
        uint32_t h01 = bf2(v.y, v.x);       // mem order: x lo, y hi
        uint32_t h23 = bf2(v.w, v.z);
        float hx = __uint_as_float(h01 << 16), hy = __uint_as_float(h01 & 0xffff0000u);
        float hz = __uint_as_float(h23 << 16), hw = __uint_as_float(h23 & 0xffff0000u);
        uint32_t l01 = bf2(v.y - hy, v.x - hx);
        uint32_t l23 = bf2(v.w - hw, v.z - hz);
        uint32_t off = pt*144 + ci4*8;
        sts64(sb + SM_AB + off, h01, h23);
        sts64(sb + SM_AS + off, l01, l23);
    }
}

// 128x64x64 with 3-term bf16 split: acc += Ah*Bh + Ah*Bl + Al*Bh
__device__ __forceinline__ void gemm_tile(uint32_t sb, float acc[2][4][4]) {
    const int tid = threadIdx.x, wid = tid >> 5, l = tid & 31;
    const int wm = (wid & 3) * 32, wn = (wid >> 2) * 32;
    const uint32_t a_r = (l & 7) + ((l >> 3) & 1) * 8;
    const uint32_t a_k = (l >> 4) * 8;
    const uint32_t b_n = l & 7;
    const uint32_t b_k = ((l >> 3) & 1) * 8;
    #pragma unroll
    for (int kk = 0; kk < 4; kk++) {
        uint32_t bb[4][2], bs[4][2];
        #pragma unroll
        for (int nb = 0; nb < 4; nb++) {
            uint32_t ba = sb + SM_BB + (wn + nb*8 + b_n)*144 + (kk*16 + b_k)*2;
            ldsm2(ba, bb[nb]);
            ldsm2(ba + (SM_BS - SM_BB), bs[nb]);
        }
        #pragma unroll
        for (int mb = 0; mb < 2; mb++) {
            uint32_t aa = sb + SM_AB + (wm + mb*16 + a_r)*144 + (kk*16 + a_k)*2;
            uint32_t ab4[4], as4[4];
            ldsm4(aa, ab4);
            ldsm4(aa + (SM_AS - SM_AB), as4);
            #pragma unroll
            for (int nb = 0; nb < 4; nb++) {
                mma_bf16(acc[mb][nb], ab4, bb[nb]);
                mma_bf16(acc[mb][nb], ab4, bs[nb]);
                mma_bf16(acc[mb][nb], as4, bb[nb]);
            }
        }
    }
}

// ---------------------------------------------------------------------------
// Center tap: out = bias + feats @ W13 (plain stores) + fused grid cleanup.
__global__ void __launch_bounds__(TPB)
center_k(const float* __restrict__ feats, const float* __restrict__ bias,
         const int* __restrict__ coords, float* __restrict__ out, int n)
{
    extern __shared__ char smem[];
    const uint32_t sb = smem_u32(smem);
    int2* pair_s = (int2*)(smem + SM_PAIRS);

    const int tid = threadIdx.x, wid = tid >> 5, l = tid & 31;
    const int p0  = blockIdx.x * 128;
    const int wm = (wid & 3) * 32, wn = (wid >> 2) * 32;

    if (tid < 128) {
        int pt = p0 + tid;
        int2 pr = make_int2(-1, -1);
        if (pt < n) {
            pr = make_int2(pt, pt);
            int4 c = ((const int4*)coords)[pt];    // fused cleanup
            g_grid[((c.x*DD + c.y)*HH + c.z)*WW + c.w] = 0;
        }
        pair_s[tid] = pr;
    }
    stage_B(sb, 13);
    __syncthreads();
    stage_A(sb, feats, pair_s);
    __syncthreads();

    float acc[2][4][4];
    #pragma unroll
    for (int nb = 0; nb < 4; nb++) {
        float2 bv = *(const float2*)(bias + wn + nb*8 + 2*(l & 3));
        #pragma unroll
        for (int mb = 0; mb < 2; mb++) {
            acc[mb][nb][0] = bv.x; acc[mb][nb][1] = bv.y;
            acc[mb][nb][2] = bv.x; acc[mb][nb][3] = bv.y;
        }
    }

    gemm_tile(sb, acc);

    #pragma unroll
    for (int mb = 0; mb < 2; mb++) {
        int r0 = p0 + wm + mb*16 + (l >> 2);
        int r1 = r0 + 8;
        #pragma unroll
        for (int nb = 0; nb < 4; nb++) {
            int col = wn + nb*8 + 2*(l & 3);
            if (r0 < n) *(float2*)(out + r0*COc + col) = make_float2(acc[mb][nb][0], acc[mb][nb][1]);
            if (r1 < n) *(float2*)(out + r1*COc + col) = make_float2(acc[mb][nb][2], acc[mb][nb][3]);
        }
    }
}

// ---------------------------------------------------------------------------
// Sparse taps: gathered mma GEMM over compacted pair lists, RED accumulate.
__global__ void __launch_bounds__(TPB)
sparse_k(const float* __restrict__ feats, float* __restrict__ out)
{
    extern __shared__ char smem[];
    const uint32_t sb = smem_u32(smem);
    int2* pair_s = (int2*)(smem + SM_PAIRS);

    const int tid = threadIdx.x, wid = tid >> 5, l = tid & 31;
    const int t   = blockIdx.y;
    const int tap = (t < 13) ? t : t + 1;
    const int cnt = g_cnt[((t < 13) ? t : 25 - t) * 32];
    const int wm = (wid & 3) * 32, wn = (wid >> 2) * 32;

    stage_B(sb, tap);

    for (int tile = blockIdx.x; tile*128 < cnt; tile += gridDim.x) {
        __syncthreads();   // prior tile's reads done before smem reuse
        if (tid < 128) {
            int p = tile*128 + tid;
            pair_s[tid] = (p < cnt) ? g_pairs[tap*NMAX + p] : make_int2(-1, -1);
        }
        __syncthreads();
        stage_A(sb, feats, pair_s);
        __syncthreads();

        float acc[2][4][4];
        #pragma unroll
        for (int mb = 0; mb < 2; mb++)
            #pragma unroll
            for (int nb = 0; nb < 4; nb++)
                #pragma unroll
                for (int k2 = 0; k2 < 4; k2++)
                    acc[mb][nb][k2] = 0.f;

        gemm_tile(sb, acc);

        #pragma unroll
        for (int mb = 0; mb < 2; mb++) {
            int row0 = wm + mb*16 + (l >> 2);
            int r0 = pair_s[row0].x;
            int r1 = pair_s[row0 + 8].x;
            #pragma unroll
            for (int nb = 0; nb < 4; nb++) {
                int col = wn + nb*8 + 2*(l & 3);
                if (r0 >= 0)
                    asm volatile("red.global.add.v2.f32 [%0], {%1,%2};"
                        :: "l"(out + r0*COc + col), "f"(acc[mb][nb][0]), "f"(acc[mb][nb][1]) : "memory");
                if (r1 >= 0)
                    asm volatile("red.global.add.v2.f32 [%0], {%1,%2};"
                        :: "l"(out + r1*COc + col), "f"(acc[mb][nb][2]), "f"(acc[mb][nb][3]) : "memory");
            }
        }
    }
}

// ---------------------------------------------------------------------------
extern "C" void kernel_launch(void* const* d_in, const int* in_sizes, int n_in,
                              void* d_out, int out_size)
{
    const float* feats  = (const float*)d_in[0];
    const float* weight = (const float*)d_in[1];
    const float* bias   = (const float*)d_in[2];
    const int*   coords = (const int*)d_in[3];
    float* out = (float*)d_out;

    int n = in_sizes[0] / CIc;

    static bool attr_set = false;
    if (!attr_set) {
        cudaFuncSetAttribute(center_k, cudaFuncAttributeMaxDynamicSharedMemorySize, SM_TOTAL);
        cudaFuncSetAttribute(sparse_k, cudaFuncAttributeMaxDynamicSharedMemorySize, SM_TOTAL);
        attr_set = true;
    }

    int prep_items = (NTAP*CIc*COc > n) ? NTAP*CIc*COc : n;
    prep_k<<<(prep_items + 255)/256, 256>>>(coords, weight, n);
    build_pairs_k<<<(n + TPB - 1)/TPB, TPB>>>(coords, n);

    int nblocks = (n + 127) / 128;
    center_k<<<nblocks, TPB, SM_TOTAL>>>(feats, bias, coords, out, n);

    dim3 sgrid(GXS, 26);
    sparse_k<<<sgrid, TPB, SM_TOTAL>>>(feats, out);
}